// round 10
// baseline (speedup 1.0000x reference)
#include <cuda_runtime.h>
#include <cuda_bf16.h>

// Problem dims
#define BB    8
#define TOUT  256
#define TIN   512
#define LL    128
#define DIN   128
#define DATT  128
#define GG    512   // 4*L

// Scratch (device globals: no allocation allowed)
__device__ float g_keys[BB * TIN * LL];    // 2 MB
__device__ float g_xz[BB * TOUT * GG];     // 4 MB

__device__ __forceinline__ float fast_tanh(float x) {
    float y;
    asm("tanh.approx.f32 %0, %1;" : "=f"(y) : "f"(x));
    return y;
}
__device__ __forceinline__ float sigm_acc(float x) {
    return 1.0f / (1.0f + __expf(-x));
}
__device__ __forceinline__ float tanh_acc(float x) {
    return 2.0f / (1.0f + __expf(-2.0f * x)) - 1.0f;
}
// packed f32x2 fma (sm_103a): d = a*b + c lanewise on 2 floats in a u64
__device__ __forceinline__ unsigned long long ffma2(unsigned long long a,
                                                    unsigned long long b,
                                                    unsigned long long c) {
    unsigned long long d;
    asm("fma.rn.f32x2 %0, %1, %2, %3;" : "=l"(d) : "l"(a), "l"(b), "l"(c));
    return d;
}
__device__ __forceinline__ unsigned long long pack2(float lo, float hi) {
    unsigned long long p;
    asm("mov.b64 %0, {%1, %2};" : "=l"(p) : "f"(lo), "f"(hi));
    return p;
}
__device__ __forceinline__ float2 unpack2(unsigned long long p) {
    float lo, hi;
    asm("mov.b64 {%0, %1}, %2;" : "=f"(lo), "=f"(hi) : "l"(p));
    return make_float2(lo, hi);
}

// ---------------------------------------------------------------------------
// Kernel 1: xz = inputs @ Wk + bias   (2048 rows x 512 cols, K=128)
// ---------------------------------------------------------------------------
__global__ void xz_kernel(const float* __restrict__ inp,
                          const float* __restrict__ Wk,
                          const float* __restrict__ bias) {
    __shared__ float a_s[16][128];
    const int tid = threadIdx.x;
    const int row0 = blockIdx.x * 16;

    const float4* src = (const float4*)(inp + row0 * DIN);
    ((float4*)&a_s[0][0])[tid] = src[tid];
    __syncthreads();

    float acc[16];
    float bj = bias[tid];
#pragma unroll
    for (int r = 0; r < 16; r++) acc[r] = bj;

    for (int d = 0; d < 128; d += 4) {
        float w0 = Wk[(d + 0) * GG + tid];
        float w1 = Wk[(d + 1) * GG + tid];
        float w2 = Wk[(d + 2) * GG + tid];
        float w3 = Wk[(d + 3) * GG + tid];
#pragma unroll
        for (int r = 0; r < 16; r++) {
            float4 a = *(const float4*)&a_s[r][d];
            acc[r] += a.x * w0 + a.y * w1 + a.z * w2 + a.w * w3;
        }
    }
#pragma unroll
    for (int r = 0; r < 16; r++)
        g_xz[(row0 + r) * GG + tid] = acc[r];
}

// ---------------------------------------------------------------------------
// Kernel 2: keys = attended @ W1 + b1  (4096 rows x 128 cols, K=128)
// ---------------------------------------------------------------------------
__global__ void keys_kernel(const float* __restrict__ att,
                            const float* __restrict__ W1,
                            const float* __restrict__ b1) {
    __shared__ float a_s[16][128];
    const int tid = threadIdx.x;
    const int row0 = blockIdx.x * 16;

    const float4* src = (const float4*)(att + row0 * DATT);
    float4* dst = (float4*)&a_s[0][0];
    for (int i = tid; i < 512; i += 128) dst[i] = src[i];
    __syncthreads();

    float acc[16];
    float bj = b1[tid];
#pragma unroll
    for (int r = 0; r < 16; r++) acc[r] = bj;

    for (int d = 0; d < 128; d += 4) {
        float w0 = W1[(d + 0) * LL + tid];
        float w1 = W1[(d + 1) * LL + tid];
        float w2 = W1[(d + 2) * LL + tid];
        float w3 = W1[(d + 3) * LL + tid];
#pragma unroll
        for (int r = 0; r < 16; r++) {
            float4 a = *(const float4*)&a_s[r][d];
            acc[r] += a.x * w0 + a.y * w1 + a.z * w2 + a.w * w3;
        }
    }
#pragma unroll
    for (int r = 0; r < 16; r++)
        g_keys[(row0 + r) * LL + tid] = acc[r];
}

// ---------------------------------------------------------------------------
// Kernel 3: LSTM scan v5 — TWO batches per CTA (weight-fetch reuse 2x).
// grid 4 (CTA x handles batches x and x+4), block 512 (thread = gate column).
// Weights row-pair packed: rows 0..87 in 44 u64 registers; rows 88..127 in
// smem (20 u64 per column, stride 44 floats = 11x16B granules, odd ->
// conflict-free LDS.128). Each weight pair multiplies BOTH batches' h-pairs.
// Per-batch h arrays read as ulonglong2 broadcasts.
// Gate nonlinearities distributed across all 512 threads (both batches).
// ---------------------------------------------------------------------------
#define WST2 44
#define LSTM_SMEM ((512 * WST2 + 256 + 1024) * 4)   // 95,232 B

__global__ void __launch_bounds__(512, 1)
lstm_kernel(const float* __restrict__ Wr, float* __restrict__ out) {
    extern __shared__ float sm[];
    float* h0_s = sm + 512 * WST2;          // [128] batch A h
    float* h1_s = h0_s + 128;               // [128] batch B h
    float* a_s  = h1_s + 128;               // [1024] activated gates (A then B)

    const int tid = threadIdx.x;
    const int b0 = blockIdx.x;              // batch A
    const int b1 = blockIdx.x + 4;          // batch B

    // rows 0..87 of this thread's column -> 44 packed register pairs
    unsigned long long w[44];
#pragma unroll
    for (int p = 0; p < 44; p++)
        w[p] = pack2(Wr[(2 * p) * GG + tid], Wr[(2 * p + 1) * GG + tid]);

    // rows 88..127 -> smem packed pairs (20 u64 per column)
    unsigned long long* wst = (unsigned long long*)(sm + tid * WST2);
#pragma unroll
    for (int p = 0; p < 20; p++)
        wst[p] = pack2(Wr[(88 + 2 * p) * GG + tid], Wr[(89 + 2 * p) * GG + tid]);

    if (tid < 128) { h0_s[tid] = 0.0f; h1_s[tid] = 0.0f; }
    float c = 0.0f;                          // used by tid<256 in tail role
    __syncthreads();

    const float* xzA = g_xz + b0 * TOUT * GG;
    const float* xzB = g_xz + b1 * TOUT * GG;
    float* outA = out + b0 * TOUT * 256;
    float* outB = out + b1 * TOUT * 256;

    float xz0 = xzA[tid];
    float xz1 = xzB[tid];

    const bool is_g = (tid >= 256) && (tid < 384);
    const int bt = tid >> 7;                 // tail: 0 -> batch A, 1 -> batch B
    const int lu = tid & 127;                // tail: unit index

    for (int t = 0; t < TOUT; t++) {
        unsigned long long aA0 = pack2(xz0, 0.0f), aA1 = 0ULL;
        unsigned long long aB0 = pack2(xz1, 0.0f), aB1 = 0ULL;

        const ulonglong2* h0v = (const ulonglong2*)h0_s;   // 16 x (4 floats)
        const ulonglong2* h1v = (const ulonglong2*)h1_s;

        // register-weight part: pairs 0..43 (rows 0..87)
#pragma unroll
        for (int j = 0; j < 22; j++) {
            ulonglong2 x0 = h0v[j];
            ulonglong2 x1 = h1v[j];
            aA0 = ffma2(w[2 * j],     x0.x, aA0);
            aA1 = ffma2(w[2 * j + 1], x0.y, aA1);
            aB0 = ffma2(w[2 * j],     x1.x, aB0);
            aB1 = ffma2(w[2 * j + 1], x1.y, aB1);
        }
        // smem-weight part: pairs 44..63 (rows 88..127)
        const ulonglong2* wp = (const ulonglong2*)wst;
#pragma unroll
        for (int r = 0; r < 10; r++) {
            ulonglong2 wv = wp[r];
            ulonglong2 x0 = h0v[22 + (r >> 1)];   // careful: see index note below
            (void)x0;
            ulonglong2 hA = h0v[22 + r - (r >> 1) * 0];  // placeholder removed below
            (void)hA;
            break;
        }
        // (indexing done explicitly to avoid mistakes)
        {
            const ulonglong2* wpv = (const ulonglong2*)wst;  // 10 entries = pairs 44..63
#pragma unroll
            for (int r = 0; r < 10; r++) {
                ulonglong2 wv = wpv[r];
                // wpv[r] holds pairs (44+2r, 44+2r+1); h pairs live at
                // ulonglong2 index 22+r (pairs 44+2r, 45+2r)
                ulonglong2 x0 = h0v[22 + r];
                ulonglong2 x1 = h1v[22 + r];
                aA0 = ffma2(wv.x, x0.x, aA0);
                aA1 = ffma2(wv.y, x0.y, aA1);
                aB0 = ffma2(wv.x, x1.x, aB0);
                aB1 = ffma2(wv.y, x1.y, aB1);
            }
        }

        float2 fA0 = unpack2(aA0), fA1 = unpack2(aA1);
        float2 fB0 = unpack2(aB0), fB1 = unpack2(aB1);
        float zA = (fA0.x + fA0.y) + (fA1.x + fA1.y);
        float zB = (fB0.x + fB0.y) + (fB1.x + fB1.y);

        // prefetch next step's xz
        if (t + 1 < TOUT) {
            xz0 = xzA[(t + 1) * GG + tid];
            xz1 = xzB[(t + 1) * GG + tid];
        }

        // distributed gate nonlinearity: own z only, both batches
        a_s[tid]       = is_g ? tanh_acc(zA) : sigm_acc(zA);
        a_s[512 + tid] = is_g ? tanh_acc(zB) : sigm_acc(zB);
        __syncthreads();

        if (tid < 256) {
            const float* base = a_s + bt * 512;
            float ai = base[lu];
            float af = base[lu + 128];
            float ag = base[lu + 256];
            float ao = base[lu + 384];
            c = af * c + ai * ag;
            float h = ao * tanh_acc(c);
            if (bt == 0) { h0_s[lu] = h; outA[t * 256 + lu] = h; }
            else         { h1_s[lu] = h; outB[t * 256 + lu] = h; }
        }
        __syncthreads();
    }

    if (tid < 256) {
        int bb = bt ? b1 : b0;
        float hT = bt ? h1_s[lu] : h0_s[lu];
        out[BB * TOUT * 256 + bb * LL + lu]           = hT;   // h_T
        out[BB * TOUT * 256 + BB * LL + bb * LL + lu] = c;    // c_T
    }
}

// ---------------------------------------------------------------------------
// Kernel 4 v5 (measured best): fused q = x@W2+b2, scores, online softmax,
// weighted sum. grid (16, 8) = 128 CTAs; block 512 = 16 warps, one q-row per
// warp. Smem 152,064 B -> 1 CTA/SM.
// ---------------------------------------------------------------------------
#define ATTN_SMEM ((128 * 132 * 2 + 16 * 128 + 16 * 128 + 128) * 4)

__global__ void __launch_bounds__(512, 1)
attn_kernel(const float* __restrict__ attg,
            const float* __restrict__ W2,
            const float* __restrict__ b2,
            const float* __restrict__ W3,
            float* __restrict__ out) {
    extern __shared__ float sm[];
    float* keys_s = sm;                     // 128*132
    float* att_s  = sm + 128 * 132;         // 128*132
    float* q_s    = sm + 2 * 128 * 132;     // 16*128
    float* p_s    = q_s + 16 * 128;         // 16*128
    float* w3_s   = p_s + 16 * 128;         // 128

    const int tid = threadIdx.x;
    const int lane = tid & 31;
    const int wid = tid >> 5;               // q-row within tile (0..15)
    const int b = blockIdx.y;
    const int t0 = blockIdx.x * 16;

    // ---- prologue: W2 into keys_s (pad 132), x rows into att_s ----
    if (tid < 128) w3_s[tid] = W3[tid];
    for (int i = tid; i < 128 * 128; i += 512) {
        int d = i >> 7, cc = i & 127;
        keys_s[d * 132 + cc] = W2[i];
    }
    for (int i = tid; i < 16 * 128; i += 512) {
        int tq = i >> 7, dd = i & 127;
        att_s[tq * 132 + dd] = out[b * (TOUT * 256) + (t0 + tq) * 256 + dd];  // x
    }
    __syncthreads();

    // q = x @ W2 + b2 : 16 rows x 128 cols, 4 outputs per thread
#pragma unroll
    for (int r = 0; r < 4; r++) {
        int i = r * 512 + tid;
        int tq = i >> 7, cc = i & 127;
        float acc = b2[cc];
        const float* xr = att_s + tq * 132;
#pragma unroll 8
        for (int d = 0; d < 128; d++)
            acc += xr[d] * keys_s[d * 132 + cc];
        q_s[tq * 128 + cc] = acc;
    }

    // per-warp state for its single q-row
    float m = -1e30f;
    float den = 0.0f;
    float4 acc = make_float4(0.f, 0.f, 0.f, 0.f);

    const float4* q4  = (const float4*)(q_s + wid * 128);
    const float4* w34 = (const float4*)w3_s;

    for (int kc = 0; kc < 4; kc++) {
        __syncthreads();  // previous chunk fully consumed (and q ready)
        const float4* ksrc = (const float4*)(g_keys + b * TIN * LL + kc * 128 * LL);
        const float4* asrc = (const float4*)(attg + b * TIN * DATT + kc * 128 * DATT);
        for (int i = tid; i < 4096; i += 512) {
            int r = i >> 5, c4 = i & 31;
            *(float4*)&keys_s[r * 132 + c4 * 4] = ksrc[i];
            *(float4*)&att_s[r * 132 + c4 * 4] = asrc[i];
        }
        __syncthreads();

        // scores: lane covers k = ks*32+lane
        float p[4] = {0.f, 0.f, 0.f, 0.f};
#pragma unroll 4
        for (int l4 = 0; l4 < 32; l4++) {
            float4 wv = w34[l4];
            float4 qv = q4[l4];
#pragma unroll
            for (int ks = 0; ks < 4; ks++) {
                float4 kv = *(const float4*)(keys_s + (ks * 32 + lane) * 132 + l4 * 4);
                p[ks] += fast_tanh(kv.x + qv.x) * wv.x + fast_tanh(kv.y + qv.y) * wv.y
                       + fast_tanh(kv.z + qv.z) * wv.z + fast_tanh(kv.w + qv.w) * wv.w;
            }
        }

        // warp max
        float s = fmaxf(fmaxf(p[0], p[1]), fmaxf(p[2], p[3]));
#pragma unroll
        for (int off = 16; off > 0; off >>= 1)
            s = fmaxf(s, __shfl_xor_sync(0xffffffffu, s, off));

        float mn = fmaxf(m, s);
        float sc = __expf(m - mn);
        den *= sc;
        acc.x *= sc; acc.y *= sc; acc.z *= sc; acc.w *= sc;
        m = mn;

#pragma unroll
        for (int ks = 0; ks < 4; ks++) {
            float e = __expf(p[ks] - mn);
            den += e;
            p_s[wid * 128 + ks * 32 + lane] = e;
        }
        __syncwarp();   // cross-lane p_s visibility within the warp

        // weighted accumulate: acc[d] += p[k] * att[k][d], lane owns d=lane*4..+3
        const float* pr = p_s + wid * 128;
#pragma unroll 2
        for (int kk = 0; kk < 128; kk++) {
            float pv = pr[kk];
            float4 av = *(const float4*)(att_s + kk * 132 + lane * 4);
            acc.x += pv * av.x; acc.y += pv * av.y;
            acc.z += pv * av.z; acc.w += pv * av.w;
        }
    }

    // reduce denominator across lanes, normalize, write weighted part
#pragma unroll
    for (int off = 16; off > 0; off >>= 1)
        den += __shfl_xor_sync(0xffffffffu, den, off);
    float inv = 1.0f / den;

    float* od = out + b * (TOUT * 256) + (t0 + wid) * 256 + 128;
    *(float4*)(od + lane * 4) = make_float4(acc.x * inv, acc.y * inv,
                                            acc.z * inv, acc.w * inv);
}

// ---------------------------------------------------------------------------
extern "C" void kernel_launch(void* const* d_in, const int* in_sizes, int n_in,
                              void* d_out, int out_size) {
    const float* inputs   = (const float*)d_in[0];
    const float* attended = (const float*)d_in[1];
    const float* Wk       = (const float*)d_in[2];
    const float* Wr       = (const float*)d_in[3];
    const float* bias     = (const float*)d_in[4];
    const float* W1       = (const float*)d_in[5];
    const float* b1       = (const float*)d_in[6];
    const float* W2       = (const float*)d_in[7];
    const float* b2       = (const float*)d_in[8];
    const float* W3       = (const float*)d_in[9];
    // d_in[10] = b3: constant shift of scores -> softmax-invariant, unused.
    float* out = (float*)d_out;

    cudaFuncSetAttribute(lstm_kernel, cudaFuncAttributeMaxDynamicSharedMemorySize, LSTM_SMEM);
    cudaFuncSetAttribute(attn_kernel, cudaFuncAttributeMaxDynamicSharedMemorySize, ATTN_SMEM);

    xz_kernel<<<128, 512>>>(inputs, Wk, bias);
    keys_kernel<<<256, 128>>>(attended, W1, b1);
    lstm_kernel<<<4, 512, LSTM_SMEM>>>(Wr, out);
    attn_kernel<<<dim3(16, 8), 512, ATTN_SMEM>>>(attended, W2, b2, W3, out);
}

// round 14
// speedup vs baseline: 1.4848x; 1.4848x over previous
#include <cuda_runtime.h>
#include <cuda_bf16.h>

// Problem dims
#define BB    8
#define TOUT  256
#define TIN   512
#define LL    128
#define DIN   128
#define DATT  128
#define GG    512   // 4*L

// Scratch (device globals: no allocation allowed)
__device__ float g_keys[BB * TIN * LL];    // 2 MB
__device__ float g_xz[BB * TOUT * GG];     // 4 MB

__device__ __forceinline__ float fast_tanh(float x) {
    float y;
    asm("tanh.approx.f32 %0, %1;" : "=f"(y) : "f"(x));
    return y;
}
__device__ __forceinline__ float sigm_acc(float x) {
    return 1.0f / (1.0f + __expf(-x));
}
__device__ __forceinline__ float tanh_acc(float x) {
    return 2.0f / (1.0f + __expf(-2.0f * x)) - 1.0f;
}
// packed f32x2 fma (sm_103a): d = a*b + c lanewise on 2 floats in a u64
__device__ __forceinline__ unsigned long long ffma2(unsigned long long a,
                                                    unsigned long long b,
                                                    unsigned long long c) {
    unsigned long long d;
    asm("fma.rn.f32x2 %0, %1, %2, %3;" : "=l"(d) : "l"(a), "l"(b), "l"(c));
    return d;
}
__device__ __forceinline__ unsigned long long pack2(float lo, float hi) {
    unsigned long long p;
    asm("mov.b64 %0, {%1, %2};" : "=l"(p) : "f"(lo), "f"(hi));
    return p;
}
__device__ __forceinline__ float2 unpack2(unsigned long long p) {
    float lo, hi;
    asm("mov.b64 {%0, %1}, %2;" : "=f"(lo), "=f"(hi) : "l"(p));
    return make_float2(lo, hi);
}

// ---------------------------------------------------------------------------
// Kernel 1: xz = inputs @ Wk + bias   (2048 rows x 512 cols, K=128)
// ---------------------------------------------------------------------------
__global__ void xz_kernel(const float* __restrict__ inp,
                          const float* __restrict__ Wk,
                          const float* __restrict__ bias) {
    __shared__ float a_s[16][128];
    const int tid = threadIdx.x;
    const int row0 = blockIdx.x * 16;

    const float4* src = (const float4*)(inp + row0 * DIN);
    ((float4*)&a_s[0][0])[tid] = src[tid];
    __syncthreads();

    float acc[16];
    float bj = bias[tid];
#pragma unroll
    for (int r = 0; r < 16; r++) acc[r] = bj;

    for (int d = 0; d < 128; d += 4) {
        float w0 = Wk[(d + 0) * GG + tid];
        float w1 = Wk[(d + 1) * GG + tid];
        float w2 = Wk[(d + 2) * GG + tid];
        float w3 = Wk[(d + 3) * GG + tid];
#pragma unroll
        for (int r = 0; r < 16; r++) {
            float4 a = *(const float4*)&a_s[r][d];
            acc[r] += a.x * w0 + a.y * w1 + a.z * w2 + a.w * w3;
        }
    }
#pragma unroll
    for (int r = 0; r < 16; r++)
        g_xz[(row0 + r) * GG + tid] = acc[r];
}

// ---------------------------------------------------------------------------
// Kernel 2: keys = attended @ W1 + b1  (4096 rows x 128 cols, K=128)
// ---------------------------------------------------------------------------
__global__ void keys_kernel(const float* __restrict__ att,
                            const float* __restrict__ W1,
                            const float* __restrict__ b1) {
    __shared__ float a_s[16][128];
    const int tid = threadIdx.x;
    const int row0 = blockIdx.x * 16;

    const float4* src = (const float4*)(att + row0 * DATT);
    float4* dst = (float4*)&a_s[0][0];
    for (int i = tid; i < 512; i += 128) dst[i] = src[i];
    __syncthreads();

    float acc[16];
    float bj = b1[tid];
#pragma unroll
    for (int r = 0; r < 16; r++) acc[r] = bj;

    for (int d = 0; d < 128; d += 4) {
        float w0 = W1[(d + 0) * LL + tid];
        float w1 = W1[(d + 1) * LL + tid];
        float w2 = W1[(d + 2) * LL + tid];
        float w3 = W1[(d + 3) * LL + tid];
#pragma unroll
        for (int r = 0; r < 16; r++) {
            float4 a = *(const float4*)&a_s[r][d];
            acc[r] += a.x * w0 + a.y * w1 + a.z * w2 + a.w * w3;
        }
    }
#pragma unroll
    for (int r = 0; r < 16; r++)
        g_keys[(row0 + r) * LL + tid] = acc[r];
}

// ---------------------------------------------------------------------------
// Kernel 3: LSTM scan v2 (measured best, ~265 us). grid 8, block 512.
// Wr rows 0..91 in registers as 46 packed f32x2 pairs per thread,
// rows 92..127 in smem (per-column packed pairs, stride 44 floats).
// Gate nonlinearities distributed across all 512 threads.
// ---------------------------------------------------------------------------
#define WSM_STRIDE 44
#define LSTM_SMEM ((512 * WSM_STRIDE + 128 + 512) * 4)   // 92,672 B

__global__ void __launch_bounds__(512, 1)
lstm_kernel(const float* __restrict__ Wr, float* __restrict__ out) {
    extern __shared__ float sm[];
    float* wsm = sm;                        // [512][44] packed pairs, rows 92..127
    float* h_s = sm + 512 * WSM_STRIDE;     // [128]
    float* a_s = h_s + 128;                 // [512] activated gates

    const int tid = threadIdx.x;
    const int b = blockIdx.x;

    // rows 0..91 of this thread's column -> 46 packed register pairs
    unsigned long long w[46];
#pragma unroll
    for (int j = 0; j < 46; j++) {
        float lo = Wr[(2 * j) * GG + tid];
        float hi = Wr[(2 * j + 1) * GG + tid];
        w[j] = pack2(lo, hi);
    }
    // rows 92..127 -> smem packed pairs (18 pairs per column)
#pragma unroll
    for (int p = 0; p < 18; p++) {
        wsm[tid * WSM_STRIDE + 2 * p]     = Wr[(92 + 2 * p) * GG + tid];
        wsm[tid * WSM_STRIDE + 2 * p + 1] = Wr[(93 + 2 * p) * GG + tid];
    }
    if (tid < 128) h_s[tid] = 0.0f;
    float c = 0.0f;
    __syncthreads();

    const float* xzb = g_xz + b * TOUT * GG;
    float* outx = out + b * TOUT * 256;
    float xz_cur = xzb[tid];

    const bool is_g = (tid >= 256) && (tid < 384);

    for (int t = 0; t < TOUT; t++) {
        unsigned long long a0 = pack2(xz_cur, 0.0f);
        unsigned long long a1 = 0ULL, a2 = 0ULL, a3 = 0ULL;

        const ulonglong2* h2 = (const ulonglong2*)h_s;
        // register-weight part: h[0..91]
#pragma unroll
        for (int j = 0; j < 23; j++) {
            ulonglong2 hv = h2[j];
            a0 = ffma2(w[2 * j],     hv.x, a0);
            a1 = ffma2(w[2 * j + 1], hv.y, a1);
        }
        // smem-weight part: h[92..127]
        const ulonglong2* wp = (const ulonglong2*)(wsm + tid * WSM_STRIDE);
#pragma unroll
        for (int r = 0; r < 9; r++) {
            ulonglong2 hv = h2[23 + r];
            ulonglong2 wv = wp[r];
            a2 = ffma2(wv.x, hv.x, a2);
            a3 = ffma2(wv.y, hv.y, a3);
        }

        float2 f0 = unpack2(a0), f1 = unpack2(a1), f2 = unpack2(a2), f3 = unpack2(a3);
        float z = ((f0.x + f0.y) + (f1.x + f1.y)) + ((f2.x + f2.y) + (f3.x + f3.y));

        // prefetch next step's xz while z settles
        if (t + 1 < TOUT) xz_cur = xzb[(t + 1) * GG + tid];

        // distributed gate nonlinearity: own z only
        a_s[tid] = is_g ? tanh_acc(z) : sigm_acc(z);
        __syncthreads();

        if (tid < 128) {
            float ai = a_s[tid];
            float af = a_s[tid + 128];
            float ag = a_s[tid + 256];
            float ao = a_s[tid + 384];
            c = af * c + ai * ag;
            float h = ao * tanh_acc(c);
            h_s[tid] = h;
            outx[t * 256 + tid] = h;
        }
        __syncthreads();
    }

    if (tid < 128) {
        out[BB * TOUT * 256 + b * LL + tid] = h_s[tid];            // h_T
        out[BB * TOUT * 256 + BB * LL + b * LL + tid] = c;         // c_T
    }
}

// ---------------------------------------------------------------------------
// Kernel 4 v5 (measured best, 74.9 us): fused q = x@W2+b2, scores, online
// softmax, weighted sum. grid (16, 8) = 128 CTAs; block 512 = 16 warps,
// one q-row per warp. Smem 152,064 B -> 1 CTA/SM.
// ---------------------------------------------------------------------------
#define ATTN_SMEM ((128 * 132 * 2 + 16 * 128 + 16 * 128 + 128) * 4)

__global__ void __launch_bounds__(512, 1)
attn_kernel(const float* __restrict__ attg,
            const float* __restrict__ W2,
            const float* __restrict__ b2,
            const float* __restrict__ W3,
            float* __restrict__ out) {
    extern __shared__ float sm[];
    float* keys_s = sm;                     // 128*132
    float* att_s  = sm + 128 * 132;         // 128*132
    float* q_s    = sm + 2 * 128 * 132;     // 16*128
    float* p_s    = q_s + 16 * 128;         // 16*128
    float* w3_s   = p_s + 16 * 128;         // 128

    const int tid = threadIdx.x;
    const int lane = tid & 31;
    const int wid = tid >> 5;               // q-row within tile (0..15)
    const int b = blockIdx.y;
    const int t0 = blockIdx.x * 16;

    // ---- prologue: W2 into keys_s (pad 132), x rows into att_s ----
    if (tid < 128) w3_s[tid] = W3[tid];
    for (int i = tid; i < 128 * 128; i += 512) {
        int d = i >> 7, cc = i & 127;
        keys_s[d * 132 + cc] = W2[i];
    }
    for (int i = tid; i < 16 * 128; i += 512) {
        int tq = i >> 7, dd = i & 127;
        att_s[tq * 132 + dd] = out[b * (TOUT * 256) + (t0 + tq) * 256 + dd];  // x
    }
    __syncthreads();

    // q = x @ W2 + b2 : 16 rows x 128 cols, 4 outputs per thread
#pragma unroll
    for (int r = 0; r < 4; r++) {
        int i = r * 512 + tid;
        int tq = i >> 7, cc = i & 127;
        float acc = b2[cc];
        const float* xr = att_s + tq * 132;
#pragma unroll 8
        for (int d = 0; d < 128; d++)
            acc += xr[d] * keys_s[d * 132 + cc];
        q_s[tq * 128 + cc] = acc;
    }

    // per-warp state for its single q-row
    float m = -1e30f;
    float den = 0.0f;
    float4 acc = make_float4(0.f, 0.f, 0.f, 0.f);

    const float4* q4  = (const float4*)(q_s + wid * 128);
    const float4* w34 = (const float4*)w3_s;

    for (int kc = 0; kc < 4; kc++) {
        __syncthreads();  // previous chunk fully consumed (and q ready)
        const float4* ksrc = (const float4*)(g_keys + b * TIN * LL + kc * 128 * LL);
        const float4* asrc = (const float4*)(attg + b * TIN * DATT + kc * 128 * DATT);
        for (int i = tid; i < 4096; i += 512) {
            int r = i >> 5, c4 = i & 31;
            *(float4*)&keys_s[r * 132 + c4 * 4] = ksrc[i];
            *(float4*)&att_s[r * 132 + c4 * 4] = asrc[i];
        }
        __syncthreads();

        // scores: lane covers k = ks*32+lane
        float p[4] = {0.f, 0.f, 0.f, 0.f};
#pragma unroll 4
        for (int l4 = 0; l4 < 32; l4++) {
            float4 wv = w34[l4];
            float4 qv = q4[l4];
#pragma unroll
            for (int ks = 0; ks < 4; ks++) {
                float4 kv = *(const float4*)(keys_s + (ks * 32 + lane) * 132 + l4 * 4);
                p[ks] += fast_tanh(kv.x + qv.x) * wv.x + fast_tanh(kv.y + qv.y) * wv.y
                       + fast_tanh(kv.z + qv.z) * wv.z + fast_tanh(kv.w + qv.w) * wv.w;
            }
        }

        // warp max
        float s = fmaxf(fmaxf(p[0], p[1]), fmaxf(p[2], p[3]));
#pragma unroll
        for (int off = 16; off > 0; off >>= 1)
            s = fmaxf(s, __shfl_xor_sync(0xffffffffu, s, off));

        float mn = fmaxf(m, s);
        float sc = __expf(m - mn);
        den *= sc;
        acc.x *= sc; acc.y *= sc; acc.z *= sc; acc.w *= sc;
        m = mn;

#pragma unroll
        for (int ks = 0; ks < 4; ks++) {
            float e = __expf(p[ks] - mn);
            den += e;
            p_s[wid * 128 + ks * 32 + lane] = e;
        }
        __syncwarp();   // cross-lane p_s visibility within the warp

        // weighted accumulate: acc[d] += p[k] * att[k][d], lane owns d=lane*4..+3
        const float* pr = p_s + wid * 128;
#pragma unroll 2
        for (int kk = 0; kk < 128; kk++) {
            float pv = pr[kk];
            float4 av = *(const float4*)(att_s + kk * 132 + lane * 4);
            acc.x += pv * av.x; acc.y += pv * av.y;
            acc.z += pv * av.z; acc.w += pv * av.w;
        }
    }

    // reduce denominator across lanes, normalize, write weighted part
#pragma unroll
    for (int off = 16; off > 0; off >>= 1)
        den += __shfl_xor_sync(0xffffffffu, den, off);
    float inv = 1.0f / den;

    float* od = out + b * (TOUT * 256) + (t0 + wid) * 256 + 128;
    *(float4*)(od + lane * 4) = make_float4(acc.x * inv, acc.y * inv,
                                            acc.z * inv, acc.w * inv);
}

// ---------------------------------------------------------------------------
extern "C" void kernel_launch(void* const* d_in, const int* in_sizes, int n_in,
                              void* d_out, int out_size) {
    const float* inputs   = (const float*)d_in[0];
    const float* attended = (const float*)d_in[1];
    const float* Wk       = (const float*)d_in[2];
    const float* Wr       = (const float*)d_in[3];
    const float* bias     = (const float*)d_in[4];
    const float* W1       = (const float*)d_in[5];
    const float* b1       = (const float*)d_in[6];
    const float* W2       = (const float*)d_in[7];
    const float* b2       = (const float*)d_in[8];
    const float* W3       = (const float*)d_in[9];
    // d_in[10] = b3: constant shift of scores -> softmax-invariant, unused.
    float* out = (float*)d_out;

    cudaFuncSetAttribute(lstm_kernel, cudaFuncAttributeMaxDynamicSharedMemorySize, LSTM_SMEM);
    cudaFuncSetAttribute(attn_kernel, cudaFuncAttributeMaxDynamicSharedMemorySize, ATTN_SMEM);

    xz_kernel<<<128, 512>>>(inputs, Wk, bias);
    keys_kernel<<<256, 128>>>(attended, W1, b1);
    lstm_kernel<<<8, 512, LSTM_SMEM>>>(Wr, out);
    attn_kernel<<<dim3(16, 8), 512, ATTN_SMEM>>>(attended, W2, b2, W3, out);
}